// round 4
// baseline (speedup 1.0000x reference)
#include <cuda_runtime.h>
#include <stdint.h>

// Problem shape (dataset-fixed). Harness supports only f32/i32/bf16 inputs, so
// the reference's uint8 arrays arrive EXPANDED: one value 0..255 per 32-bit
// element (int32 or float32 — detected at runtime).
//   weights: 524288 elems   (2048*256 bytes, expanded)
//   flip:    16777216 elems (32*2048*256 bytes, expanded)
//   out:     524289 f32 (new_weights byte values ++ update_ratio)  [or 524288 i32]
#define WORDS       131072            // packed uint32 words = 2048*256/4
#define LAYERS      32
#define TOTAL_BITS  4194304           // 2048*2048 bit positions
#define LAYER_U4    131072            // uint4 per layer (524288 elems / 4)
#define FLIP_ELEMS  16777216
#define W_ELEMS     524288

// Scratch (static device globals only — no allocation allowed)
__device__ unsigned long long g_total;
__device__ unsigned long long g_maskpop;
__device__ unsigned int       g_isfloat;
__device__ unsigned char      g_counts[WORDS * 32];   // 4 MB: [word][bit] counts 0..32

// Detect expansion dtype + zero accumulators. int32 values 0..255 never set
// bits >= 8; float32 encodings of values >= 1.0 always set exponent bits.
__global__ void k_init(const uint32_t* __restrict__ flip_raw)
{
    uint32_t o = 0;
    #pragma unroll
    for (int i = 0; i < 64; i++) o |= flip_raw[i];
    g_isfloat = (o >> 9) ? 1u : 0u;
    g_total = 0ull; g_maskpop = 0ull;
}

// one expanded element -> byte value 0..255
__device__ __forceinline__ uint32_t bval(uint32_t r, uint32_t isf)
{
    return isf ? (uint32_t)__uint_as_float(r) : r;
}
// 4 expanded elements -> one packed byte word (elem k -> byte k)
__device__ __forceinline__ uint32_t pack4(uint4 v, uint32_t isf)
{
    uint32_t b0 = bval(v.x, isf), b1 = bval(v.y, isf);
    uint32_t b2 = bval(v.z, isf), b3 = bval(v.w, isf);
    return __byte_perm(__byte_perm(b0, b1, 0x0040),
                       __byte_perm(b2, b3, 0x0040), 0x5410);
}

// ---------------------------------------------------------------------------
// k_count: per warp, 32 packed word-columns x 32 layers. Each lane packs one
// word per layer (coalesced uint4 load), tile in padded SMEM, then a 32x32
// warp bit-transpose puts the 32-layer column of bit i in lane i; __popc
// yields the vote count for that bit position.
// ---------------------------------------------------------------------------
__global__ void __launch_bounds__(256) k_count(const uint4* __restrict__ flip4)
{
    __shared__ uint32_t tile[8][32][33];   // [warp][layer][word], pad -> conflict-free
    const int warp = threadIdx.x >> 5;
    const int lane = threadIdx.x & 31;
    const int w0   = (blockIdx.x * 8 + warp) * 32;   // first packed word of tile
    const uint32_t isf = g_isfloat;

    #pragma unroll 8
    for (int l = 0; l < LAYERS; l++) {
        uint4 v = flip4[(size_t)l * LAYER_U4 + w0 + lane];
        tile[warp][l][lane] = pack4(v, isf);
    }
    __syncwarp();

    const uint32_t LO[5] = {0x0000FFFFu, 0x00FF00FFu, 0x0F0F0F0Fu, 0x33333333u, 0x55555555u};

    unsigned int lanesum = 0;
    #pragma unroll 4
    for (int wi = 0; wi < 32; wi++) {
        uint32_t x = tile[warp][lane][wi];   // lane l holds layer l's packed word
        #pragma unroll
        for (int k = 0; k < 5; k++) {        // 32x32 bit transpose across lanes
            const int s = 16 >> k;
            const uint32_t lo = LO[k];
            uint32_t y = __shfl_xor_sync(0xFFFFFFFFu, x, s);
            if ((lane & s) == 0) x = (x & lo)  | ((y & lo)  << s);
            else                 x = (x & ~lo) | ((y & ~lo) >> s);
        }
        unsigned int cnt = __popc(x);        // votes for bit 'lane' of word w0+wi
        lanesum += cnt;
        g_counts[(size_t)(w0 + wi) * 32 + lane] = (unsigned char)cnt;
    }

    #pragma unroll
    for (int s = 16; s; s >>= 1) lanesum += __shfl_xor_sync(0xFFFFFFFFu, lanesum, s);
    __shared__ unsigned int bsum;
    if (threadIdx.x == 0) bsum = 0;
    __syncthreads();
    if (lane == 0) atomicAdd(&bsum, lanesum);
    __syncthreads();
    if (threadIdx.x == 0) atomicAdd(&g_total, (unsigned long long)bsum);
}

// ---------------------------------------------------------------------------
// k_mask: threshold, packed mask, XNOR with (repacked) weights, write output,
// accumulate mask popcount.
// ---------------------------------------------------------------------------
__global__ void __launch_bounds__(256) k_mask(const uint4* __restrict__ weights4,
                                              const float* __restrict__ vpm,
                                              float* __restrict__ outf,
                                              int* __restrict__ outi,
                                              int as_float)
{
    const int w = blockIdx.x * blockDim.x + threadIdx.x;   // packed word 0..WORDS-1
    const uint32_t isf = g_isfloat;

    // p = max(vote_p_max, mean/32); mask = votes > p*32. votes integer:
    //   votes > th  <=>  votes > floor(th)
    const float mean = (float)((double)g_total * (1.0 / (double)TOTAL_BITS));
    const float p    = fmaxf(vpm[0], mean * (1.0f / 32.0f));
    const unsigned int tb = (unsigned int)floorf(p * 32.0f);

    const uint4 c0 = ((const uint4*)g_counts)[w * 2 + 0];
    const uint4 c1 = ((const uint4*)g_counts)[w * 2 + 1];
    const uint32_t cs[8] = {c0.x, c0.y, c0.z, c0.w, c1.x, c1.y, c1.z, c1.w};

    uint32_t mask = 0;
    #pragma unroll
    for (int k = 0; k < 8; k++)
        #pragma unroll
        for (int j = 0; j < 4; j++) {
            unsigned int cnt = (cs[k] >> (8 * j)) & 0xFFu;
            mask |= (cnt > tb ? 1u : 0u) << (k * 4 + j);
        }

    const uint32_t wword = pack4(weights4[w], isf);
    const uint32_t xw    = ~(mask ^ wword);          // bytewise XNOR

    if (as_float) {
        float4 o;
        o.x = (float)( xw        & 0xFFu);
        o.y = (float)((xw >> 8)  & 0xFFu);
        o.z = (float)((xw >> 16) & 0xFFu);
        o.w = (float)((xw >> 24) & 0xFFu);
        ((float4*)outf)[w] = o;
    } else {
        int4 o;
        o.x = (int)( xw        & 0xFFu);
        o.y = (int)((xw >> 8)  & 0xFFu);
        o.z = (int)((xw >> 16) & 0xFFu);
        o.w = (int)((xw >> 24) & 0xFFu);
        ((int4*)outi)[w] = o;
    }

    unsigned int mp = __popc(mask);
    #pragma unroll
    for (int s = 16; s; s >>= 1) mp += __shfl_xor_sync(0xFFFFFFFFu, mp, s);
    __shared__ unsigned int bsum;
    if (threadIdx.x == 0) bsum = 0;
    __syncthreads();
    if ((threadIdx.x & 31) == 0) atomicAdd(&bsum, mp);
    __syncthreads();
    if (threadIdx.x == 0) atomicAdd(&g_maskpop, (unsigned long long)bsum);
}

__global__ void k_fin(float* __restrict__ outf, int write_ratio)
{
    if (write_ratio)
        outf[W_ELEMS] = (float)((double)g_maskpop * (1.0 / (double)TOTAL_BITS));
}

extern "C" void kernel_launch(void* const* d_in, const int* in_sizes, int n_in,
                              void* d_out, int out_size)
{
    // Bind by element count (expansion preserves counts):
    //   flip = 16777216 elems, weights = 524288 elems,
    //   vote_p_max = LAST 1-elem input (after n_votes in both dict and
    //   alphabetical order).
    const uint4* weights4 = 0;
    const uint4* flip4    = 0;
    const float* vpm      = 0;
    for (int i = 0; i < n_in; i++) {
        if      (in_sizes[i] == FLIP_ELEMS) flip4    = (const uint4*)d_in[i];
        else if (in_sizes[i] == W_ELEMS)    weights4 = (const uint4*)d_in[i];
        else if (in_sizes[i] == 1)          vpm      = (const float*)d_in[i];
    }
    if (!weights4 || !flip4) {
        weights4 = (const uint4*)d_in[0];
        flip4    = (const uint4*)d_in[1];
        vpm      = (const float*)d_in[n_in - 1];
    }

    const int as_float = (out_size != W_ELEMS) ? 1 : 0;

    k_init<<<1, 1>>>((const uint32_t*)flip4);
    k_count<<<WORDS / 256, 256>>>(flip4);
    k_mask<<<WORDS / 256, 256>>>(weights4, vpm,
                                 (float*)d_out, (int*)d_out, as_float);
    k_fin<<<1, 1>>>((float*)d_out, as_float);
}